// round 15
// baseline (speedup 1.0000x reference)
#include <cuda_runtime.h>
#include <cuda_bf16.h>
#include <mma.h>
#include <cstdint>

using namespace nvcuda;

#define NS    150
#define BATCH 32
#define DIN   1024
#define DH    512
#define DOUT  256

#define L1B (NS * (DH / 64))      // 1200 layer-1 tiles
#define L2B (NS * (DOUT / 64))    // 600 layer-2 tiles

// -------------------- scratch (no cudaMalloc allowed) --------------------
__device__ float g_sW1[DH * DIN];                 // exp(v_W1)
__device__ float g_sW2[DOUT * DH];                // exp(v_W2)
__device__ __nv_bfloat16 g_xhi[BATCH * DIN];      // x split hi
__device__ __nv_bfloat16 g_xlo[BATCH * DIN];      // x split lo
__device__ __nv_bfloat16 g_Hhi[NS * BATCH * DH];  // h split hi
__device__ __nv_bfloat16 g_Hlo[NS * BATCH * DH];  // h split lo
__device__ int g_done1[NS];

// -------------------- pipe-steered add: IMAD (fma pipe), bit-identical a+b ------
__device__ __forceinline__ unsigned addi(unsigned a, unsigned one, unsigned b)
{
    unsigned d;
    asm("mad.lo.u32 %0, %1, %2, %3;" : "=r"(d) : "r"(a), "r"(one), "r"(b));
    return d;
}

// -------------------- threefry2x32 (JAX-exact, frozen semantics) --------------------
__device__ __forceinline__ void tf2x32(unsigned k0, unsigned k1,
                                       unsigned x0, unsigned x1,
                                       unsigned& o0, unsigned& o1)
{
    const unsigned ks2 = k0 ^ k1 ^ 0x1BD11BDAu;
    x0 += k0; x1 += k1;
#define TF_RND(r) { x0 += x1; x1 = __funnelshift_l(x1, x1, (r)); x1 ^= x0; }
    TF_RND(13) TF_RND(15) TF_RND(26) TF_RND(6)   x0 += k1;  x1 += ks2 + 1u;
    TF_RND(17) TF_RND(29) TF_RND(16) TF_RND(24)  x0 += ks2; x1 += k0  + 2u;
    TF_RND(13) TF_RND(15) TF_RND(26) TF_RND(6)   x0 += k0;  x1 += k1  + 3u;
    TF_RND(17) TF_RND(29) TF_RND(16) TF_RND(24)  x0 += k1;  x1 += ks2 + 4u;
    TF_RND(13) TF_RND(15) TF_RND(26) TF_RND(6)   x0 += ks2; x1 += k0  + 5u;
#undef TF_RND
    o0 = x0; o1 = x1;
}

__device__ __forceinline__ float bits_to_normal(unsigned bits)
{
    float f = __uint_as_float((bits >> 9) | 0x3f800000u) - 1.0f;
    float x = fmaf(f, 2.0f, -0.99999994f);
    float w = -__logf(fmaf(-x, x, 1.0f));
    float p;
    if (__builtin_expect(w < 5.0f, 1)) {
        w -= 2.5f;
        p = 3.9742706e-08f;
        p = fmaf(p, w, 4.8546428e-07f);
        p = fmaf(p, w, -4.9828470e-06f);
        p = fmaf(p, w, -6.2105274e-06f);
        p = fmaf(p, w, 3.0912157e-04f);
        p = fmaf(p, w, -1.7730353e-03f);
        p = fmaf(p, w, -5.9081528e-03f);
        p = fmaf(p, w, 3.4876418e-01f);
        p = fmaf(p, w, 2.1233185e+00f);
    } else {
        w = sqrtf(w) - 3.0f;
        p = -2.8314684e-04f;
        p = fmaf(p, w, 1.4276577e-04f);
        p = fmaf(p, w, 1.9082628e-03f);
        p = fmaf(p, w, -5.1950289e-03f);
        p = fmaf(p, w, 8.1169003e-03f);
        p = fmaf(p, w, -1.0779794e-02f);
        p = fmaf(p, w, 1.3348587e-02f);
        p = fmaf(p, w, 1.4165829e+00f);
        p = fmaf(p, w, 4.0064237e+00f);
    }
    return p * x;
}

__device__ __forceinline__ float tf_normal(unsigned k0, unsigned k1, unsigned e)
{
    unsigned o0, o1;
    tf2x32(k0, k1, 0u, e, o0, o1);
    return bits_to_normal(o0 ^ o1);
}

// 4 interleaved threefry chains; round-adds AND inject-adds steered onto the
// FMA pipe (IMAD) -> balanced ~46:46 ALU:FMA mix per normal.
__device__ __forceinline__ void tf_normal4(unsigned k0, unsigned k1, unsigned e,
                                           unsigned one, float r[4])
{
    const unsigned ks2 = k0 ^ k1 ^ 0x1BD11BDAu;
    unsigned a[4], b[4];
#pragma unroll
    for (int i = 0; i < 4; i++) { a[i] = k0; b[i] = addi(e + (unsigned)i, one, k1); }
#define TF_R4(rr) _Pragma("unroll") \
    for (int i = 0; i < 4; i++) { a[i] = addi(a[i], one, b[i]); b[i] = __funnelshift_l(b[i], b[i], (rr)); b[i] ^= a[i]; }
#define TF_INJ4(ka, kb, g) { unsigned _kbg = (kb) + (g); _Pragma("unroll") \
    for (int i = 0; i < 4; i++) { a[i] = addi(a[i], one, (ka)); b[i] = addi(b[i], one, _kbg); } }
    TF_R4(13) TF_R4(15) TF_R4(26) TF_R4(6)   TF_INJ4(k1,  ks2, 1u)
    TF_R4(17) TF_R4(29) TF_R4(16) TF_R4(24)  TF_INJ4(ks2, k0,  2u)
    TF_R4(13) TF_R4(15) TF_R4(26) TF_R4(6)   TF_INJ4(k0,  k1,  3u)
    TF_R4(17) TF_R4(29) TF_R4(16) TF_R4(24)  TF_INJ4(k1,  ks2, 4u)
    TF_R4(13) TF_R4(15) TF_R4(26) TF_R4(6)   TF_INJ4(ks2, k0,  5u)
#undef TF_R4
#undef TF_INJ4
#pragma unroll
    for (int i = 0; i < 4; i++) r[i] = bits_to_normal(a[i] ^ b[i]);
}

__device__ __forceinline__ unsigned pack_bf16x2(float hi, float lo)
{
    unsigned r;
    asm("cvt.rn.bf16x2.f32 %0, %1, %2;" : "=r"(r) : "f"(hi), "f"(lo));
    return r;
}

// -------------------- shared-memory layout (union: W bufs / D epilogue) ----------
#define CTILE 64
#define KCH   32
#define WST   40
#define DST   36

struct WBufs {
    __nv_bfloat16 Whi[2][CTILE * WST];
    __nv_bfloat16 Wlo[2][CTILE * WST];
};
union SmemU {
    WBufs w;
    float Dsm[CTILE * DST];
};

// -------------------- prep: exp(v_W), x bf16 split, reset counters ---------------
__global__ __launch_bounds__(256) void prep_kernel(const float* __restrict__ x,
                                                   const float* __restrict__ vW1,
                                                   const float* __restrict__ vW2)
{
    int i = blockIdx.x * 256 + threadIdx.x;
    if (i < DH * DIN)  g_sW1[i] = expf(vW1[i]);
    if (i < DOUT * DH) g_sW2[i] = expf(vW2[i]);
    if (i < BATCH * DIN) {
        float xv = x[i];
        __nv_bfloat16 hi = __float2bfloat16_rn(xv);
        __nv_bfloat16 lo = __float2bfloat16_rn(xv - __bfloat162float(hi));
        g_xhi[i] = hi; g_xlo[i] = lo;
    }
    if (i < NS) g_done1[i] = 0;
}

// -------------------- one fused 64-wide tile (frozen body + pipe steering) --------
template<int K, int NOUT, bool LAST>
__device__ __forceinline__ void tile64(
    int n, int c0, SmemU& sm,
    const float* __restrict__ mu, const float* __restrict__ s,
    const float* __restrict__ mub, const float* __restrict__ vb,
    const __nv_bfloat16* __restrict__ Bhi, const __nv_bfloat16* __restrict__ Blo,
    float* __restrict__ Out,
    unsigned wk0, unsigned wk1, unsigned bk0, unsigned bk1,
    unsigned one, long long bStride)
{
    const int tid  = threadIdx.x;
    const int warp = tid >> 5;

    const int qk    = (tid & 7) * 4;    // lane-octet -> one 128B mu/s line
    const int rbase = tid >> 3;

    const int ec = tid & 63;
    const int eb = (tid >> 6) * 16;

    float bias;
    {
        int c = c0 + ec;
        float eps = tf_normal(bk0, bk1, (unsigned)(n * NOUT + c));
        bias = fmaf(eps, expf(vb[c]), mub[c]);
    }

    wmma::fragment<wmma::accumulator, 16, 16, 16, float> acc[2];
    wmma::fill_fragment(acc[0], 0.0f);
    wmma::fill_fragment(acc[1], 0.0f);

    const unsigned ebase = (unsigned)(n * NOUT + c0) * (unsigned)K;
    const __nv_bfloat16* bh = Bhi + (size_t)n * bStride;
    const __nv_bfloat16* bl = Blo + (size_t)n * bStride;

    for (int k0 = 0; k0 < K; k0 += KCH) {
        const int buf = (k0 >> 5) & 1;
#pragma unroll 2
        for (int q = 0; q < 4; q++) {
            const int row = rbase + q * 16;
            const size_t goff = (size_t)(c0 + row) * K + k0 + qk;
            float4 m  = *reinterpret_cast<const float4*>(mu + goff);
            float4 sv = *reinterpret_cast<const float4*>(s  + goff);
            float r4[4];
            tf_normal4(wk0, wk1, ebase + (unsigned)(row * K + k0 + qk), one, r4);
            float w0 = fmaf(r4[0], sv.x, m.x);
            float w1 = fmaf(r4[1], sv.y, m.y);
            float w2 = fmaf(r4[2], sv.z, m.z);
            float w3 = fmaf(r4[3], sv.w, m.w);
            unsigned hp0 = pack_bf16x2(w1, w0);
            unsigned hp1 = pack_bf16x2(w3, w2);
            float h0 = __uint_as_float(hp0 << 16);
            float h1 = __uint_as_float(hp0 & 0xFFFF0000u);
            float h2 = __uint_as_float(hp1 << 16);
            float h3 = __uint_as_float(hp1 & 0xFFFF0000u);
            unsigned lp0 = pack_bf16x2(w1 - h1, w0 - h0);
            unsigned lp1 = pack_bf16x2(w3 - h3, w2 - h2);
            int off = row * WST + qk;
            *reinterpret_cast<uint2*>(&sm.w.Whi[buf][off]) = make_uint2(hp0, hp1);
            *reinterpret_cast<uint2*>(&sm.w.Wlo[buf][off]) = make_uint2(lp0, lp1);
        }
        __syncthreads();

#pragma unroll
        for (int kk = 0; kk < KCH; kk += 16) {
            wmma::fragment<wmma::matrix_a, 16, 16, 16, __nv_bfloat16, wmma::row_major> ahi, alo;
            wmma::load_matrix_sync(ahi, &sm.w.Whi[buf][warp * 16 * WST + kk], WST);
            wmma::load_matrix_sync(alo, &sm.w.Wlo[buf][warp * 16 * WST + kk], WST);
#pragma unroll
            for (int nb = 0; nb < 2; nb++) {
                wmma::fragment<wmma::matrix_b, 16, 16, 16, __nv_bfloat16, wmma::col_major> bhf, blf;
                wmma::load_matrix_sync(bhf, bh + (size_t)(nb * 16) * K + (k0 + kk), K);
                wmma::load_matrix_sync(blf, bl + (size_t)(nb * 16) * K + (k0 + kk), K);
                wmma::mma_sync(acc[nb], ahi, bhf, acc[nb]);
                wmma::mma_sync(acc[nb], ahi, blf, acc[nb]);
                wmma::mma_sync(acc[nb], alo, bhf, acc[nb]);
            }
        }
    }

    __syncthreads();
    wmma::store_matrix_sync(&sm.Dsm[warp * 16 * DST + 0],  acc[0], DST, wmma::mem_row_major);
    wmma::store_matrix_sync(&sm.Dsm[warp * 16 * DST + 16], acc[1], DST, wmma::mem_row_major);
    __syncthreads();

#pragma unroll
    for (int b = eb; b < eb + 16; b++) {
        float v = sm.Dsm[ec * DST + b] + bias;
        if (!LAST) {
            v = fmaxf(v, 0.0f);
            __nv_bfloat16 hi = __float2bfloat16_rn(v);
            __nv_bfloat16 lo = __float2bfloat16_rn(v - __bfloat162float(hi));
            size_t o = ((size_t)n * BATCH + b) * NOUT + (c0 + ec);
            g_Hhi[o] = hi; g_Hlo[o] = lo;
        } else {
            Out[((size_t)n * BATCH + b) * NOUT + (c0 + ec)] = v;
        }
    }
}

// -------------------- merged launch: L1 tiles then L2 tiles, static map ----------
__global__ __launch_bounds__(128, 5) void fused_all(
    const float* __restrict__ muW1, const float* __restrict__ mub1,
    const float* __restrict__ vb1,
    const float* __restrict__ muW2, const float* __restrict__ mub2,
    const float* __restrict__ vb2,
    float* __restrict__ out,
    unsigned k10, unsigned k11, unsigned k20, unsigned k21,
    unsigned k30, unsigned k31, unsigned k40, unsigned k41,
    unsigned one)
{
    __shared__ SmemU sm;
    const int bid = blockIdx.x;

    if (bid < L1B) {
        const int n = bid >> 3;             // 8 tiles per sample
        const int c0 = (bid & 7) * 64;
        tile64<DIN, DH, false>(n, c0, sm, muW1, g_sW1, mub1, vb1,
                               g_xhi, g_xlo, nullptr,
                               k10, k11, k20, k21, one, 0LL);
        __syncthreads();
        if (threadIdx.x == 0) {
            __threadfence();                // release H
            atomicAdd(&g_done1[n], 1);
        }
    } else {
        const int b2 = bid - L1B;
        const int n = b2 >> 2;              // 4 tiles per sample
        const int c0 = (b2 & 3) * 64;
        if (threadIdx.x == 0) {
            while (*(volatile int*)&g_done1[n] < 8) __nanosleep(64);
            __threadfence();                // acquire H
        }
        __syncthreads();
        tile64<DH, DOUT, true>(n, c0, sm, muW2, g_sW2, mub2, vb2,
                               g_Hhi, g_Hlo, out,
                               k30, k31, k40, k41, one, (long long)(BATCH * DH));
    }
}

// -------------------- host-side threefry for subkey derivation --------------------
static inline unsigned h_rotl(unsigned x, int r) { return (x << r) | (x >> (32 - r)); }
static void h_tf2x32(unsigned k0, unsigned k1, unsigned x0, unsigned x1,
                     unsigned& o0, unsigned& o1)
{
    const unsigned ks2 = k0 ^ k1 ^ 0x1BD11BDAu;
    x0 += k0; x1 += k1;
    static const int R[2][4] = {{13, 15, 26, 6}, {17, 29, 16, 24}};
    const unsigned ks[3] = {k0, k1, ks2};
    for (int g = 0; g < 5; g++) {
        for (int r = 0; r < 4; r++) {
            x0 += x1; x1 = h_rotl(x1, R[g & 1][r]); x1 ^= x0;
        }
        x0 += ks[(g + 1) % 3];
        x1 += ks[(g + 2) % 3] + (unsigned)(g + 1);
    }
    o0 = x0; o1 = x1;
}

extern "C" void kernel_launch(void* const* d_in, const int* in_sizes, int n_in,
                              void* d_out, int out_size)
{
    const float* x    = (const float*)d_in[0];
    const float* muW1 = (const float*)d_in[1];
    const float* mub1 = (const float*)d_in[2];
    const float* muW2 = (const float*)d_in[3];
    const float* mub2 = (const float*)d_in[4];
    const float* vW1  = (const float*)d_in[5];
    const float* vb1  = (const float*)d_in[6];
    const float* vW2  = (const float*)d_in[7];
    const float* vb2  = (const float*)d_in[8];
    float* out = (float*)d_out;

    unsigned keys[4][2];
    for (unsigned i = 0; i < 4; i++)
        h_tf2x32(0u, 42u, 0u, i, keys[i][0], keys[i][1]);

    prep_kernel<<<(DH * DIN + 255) / 256, 256>>>(x, vW1, vW2);

    fused_all<<<L1B + L2B, 128>>>(
        muW1, mub1, vb1, muW2, mub2, vb2, out,
        keys[0][0], keys[0][1], keys[1][0], keys[1][1],
        keys[2][0], keys[2][1], keys[3][0], keys[3][1],
        1u /* opaque multiplier: steers round+inject adds onto the IMAD/FMA pipe */);
}

// round 16
// speedup vs baseline: 1.0879x; 1.0879x over previous
#include <cuda_runtime.h>
#include <cuda_bf16.h>
#include <mma.h>
#include <cstdint>

using namespace nvcuda;

#define NS    150
#define BATCH 32
#define DIN   1024
#define DH    512
#define DOUT  256

#define L1B (NS * (DH / 64))      // 1200 layer-1 tiles
#define L2B (NS * (DOUT / 64))    // 600 layer-2 tiles

// -------------------- scratch (no cudaMalloc allowed) --------------------
__device__ float g_sW1[DH * DIN];                 // exp(v_W1)
__device__ float g_sW2[DOUT * DH];                // exp(v_W2)
__device__ __nv_bfloat16 g_xhi[BATCH * DIN];      // x split hi
__device__ __nv_bfloat16 g_xlo[BATCH * DIN];      // x split lo
__device__ __nv_bfloat16 g_Hhi[NS * BATCH * DH];  // h split hi
__device__ __nv_bfloat16 g_Hlo[NS * BATCH * DH];  // h split lo
__device__ int g_done1[NS];

// -------------------- pipe-steered add: IMAD (fma pipe), bit-identical a+b ------
__device__ __forceinline__ unsigned addi(unsigned a, unsigned one, unsigned b)
{
    unsigned d;
    asm("mad.lo.u32 %0, %1, %2, %3;" : "=r"(d) : "r"(a), "r"(one), "r"(b));
    return d;
}

// -------------------- threefry2x32 (JAX-exact, frozen semantics) --------------------
__device__ __forceinline__ void tf2x32(unsigned k0, unsigned k1,
                                       unsigned x0, unsigned x1,
                                       unsigned& o0, unsigned& o1)
{
    const unsigned ks2 = k0 ^ k1 ^ 0x1BD11BDAu;
    x0 += k0; x1 += k1;
#define TF_RND(r) { x0 += x1; x1 = __funnelshift_l(x1, x1, (r)); x1 ^= x0; }
    TF_RND(13) TF_RND(15) TF_RND(26) TF_RND(6)   x0 += k1;  x1 += ks2 + 1u;
    TF_RND(17) TF_RND(29) TF_RND(16) TF_RND(24)  x0 += ks2; x1 += k0  + 2u;
    TF_RND(13) TF_RND(15) TF_RND(26) TF_RND(6)   x0 += k0;  x1 += k1  + 3u;
    TF_RND(17) TF_RND(29) TF_RND(16) TF_RND(24)  x0 += k1;  x1 += ks2 + 4u;
    TF_RND(13) TF_RND(15) TF_RND(26) TF_RND(6)   x0 += ks2; x1 += k0  + 5u;
#undef TF_RND
    o0 = x0; o1 = x1;
}

__device__ __forceinline__ float bits_to_normal(unsigned bits)
{
    float f = __uint_as_float((bits >> 9) | 0x3f800000u) - 1.0f;
    float x = fmaf(f, 2.0f, -0.99999994f);
    float w = -__logf(fmaf(-x, x, 1.0f));
    float p;
    if (__builtin_expect(w < 5.0f, 1)) {
        w -= 2.5f;
        p = 3.9742706e-08f;
        p = fmaf(p, w, 4.8546428e-07f);
        p = fmaf(p, w, -4.9828470e-06f);
        p = fmaf(p, w, -6.2105274e-06f);
        p = fmaf(p, w, 3.0912157e-04f);
        p = fmaf(p, w, -1.7730353e-03f);
        p = fmaf(p, w, -5.9081528e-03f);
        p = fmaf(p, w, 3.4876418e-01f);
        p = fmaf(p, w, 2.1233185e+00f);
    } else {
        w = sqrtf(w) - 3.0f;
        p = -2.8314684e-04f;
        p = fmaf(p, w, 1.4276577e-04f);
        p = fmaf(p, w, 1.9082628e-03f);
        p = fmaf(p, w, -5.1950289e-03f);
        p = fmaf(p, w, 8.1169003e-03f);
        p = fmaf(p, w, -1.0779794e-02f);
        p = fmaf(p, w, 1.3348587e-02f);
        p = fmaf(p, w, 1.4165829e+00f);
        p = fmaf(p, w, 4.0064237e+00f);
    }
    return p * x;
}

__device__ __forceinline__ float tf_normal(unsigned k0, unsigned k1, unsigned e)
{
    unsigned o0, o1;
    tf2x32(k0, k1, 0u, e, o0, o1);
    return bits_to_normal(o0 ^ o1);
}

// 4 interleaved threefry chains; adds steered onto the FMA pipe (IMAD).
__device__ __forceinline__ void tf_normal4(unsigned k0, unsigned k1, unsigned e,
                                           unsigned one, float r[4])
{
    const unsigned ks2 = k0 ^ k1 ^ 0x1BD11BDAu;
    unsigned a[4], b[4];
#pragma unroll
    for (int i = 0; i < 4; i++) { a[i] = k0; b[i] = addi(e + (unsigned)i, one, k1); }
#define TF_R4(rr) _Pragma("unroll") \
    for (int i = 0; i < 4; i++) { a[i] = addi(a[i], one, b[i]); b[i] = __funnelshift_l(b[i], b[i], (rr)); b[i] ^= a[i]; }
#define TF_INJ4(ka, kb, g) { unsigned _kbg = (kb) + (g); _Pragma("unroll") \
    for (int i = 0; i < 4; i++) { a[i] = addi(a[i], one, (ka)); b[i] = addi(b[i], one, _kbg); } }
    TF_R4(13) TF_R4(15) TF_R4(26) TF_R4(6)   TF_INJ4(k1,  ks2, 1u)
    TF_R4(17) TF_R4(29) TF_R4(16) TF_R4(24)  TF_INJ4(ks2, k0,  2u)
    TF_R4(13) TF_R4(15) TF_R4(26) TF_R4(6)   TF_INJ4(k0,  k1,  3u)
    TF_R4(17) TF_R4(29) TF_R4(16) TF_R4(24)  TF_INJ4(k1,  ks2, 4u)
    TF_R4(13) TF_R4(15) TF_R4(26) TF_R4(6)   TF_INJ4(ks2, k0,  5u)
#undef TF_R4
#undef TF_INJ4
#pragma unroll
    for (int i = 0; i < 4; i++) r[i] = bits_to_normal(a[i] ^ b[i]);
}

__device__ __forceinline__ unsigned pack_bf16x2(float hi, float lo)
{
    unsigned r;
    asm("cvt.rn.bf16x2.f32 %0, %1, %2;" : "=r"(r) : "f"(hi), "f"(lo));
    return r;
}

// -------------------- shared-memory layout (union: W/B bufs / D epilogue) --------
#define CTILE 64
#define KCH   32
#define WST   40     // W smem stride in bf16 (80B rows; LDSM conflict-free)
#define BST   40     // B smem stride in bf16
#define DST   36

struct WBufs {
    __nv_bfloat16 Whi[2][CTILE * WST];
    __nv_bfloat16 Wlo[2][CTILE * WST];
    __nv_bfloat16 Bhi[2][32 * BST];    // staged x/H chunk, hi split
    __nv_bfloat16 Blo[2][32 * BST];    // staged x/H chunk, lo split
};
union SmemU {
    WBufs w;
    float Dsm[CTILE * DST];
};

// -------------------- prep: exp(v_W), x bf16 split, reset counters ---------------
__global__ __launch_bounds__(256) void prep_kernel(const float* __restrict__ x,
                                                   const float* __restrict__ vW1,
                                                   const float* __restrict__ vW2)
{
    int i = blockIdx.x * 256 + threadIdx.x;
    if (i < DH * DIN)  g_sW1[i] = expf(vW1[i]);
    if (i < DOUT * DH) g_sW2[i] = expf(vW2[i]);
    if (i < BATCH * DIN) {
        float xv = x[i];
        __nv_bfloat16 hi = __float2bfloat16_rn(xv);
        __nv_bfloat16 lo = __float2bfloat16_rn(xv - __bfloat162float(hi));
        g_xhi[i] = hi; g_xlo[i] = lo;
    }
    if (i < NS) g_done1[i] = 0;
}

// -------------------- one fused 64-wide tile (smem-staged B) ---------------------
template<int K, int NOUT, bool LAST>
__device__ __forceinline__ void tile64(
    int n, int c0, SmemU& sm,
    const float* __restrict__ mu, const float* __restrict__ s,
    const float* __restrict__ mub, const float* __restrict__ vb,
    const __nv_bfloat16* __restrict__ Bhi, const __nv_bfloat16* __restrict__ Blo,
    float* __restrict__ Out,
    unsigned wk0, unsigned wk1, unsigned bk0, unsigned bk1,
    unsigned one, long long bStride)
{
    const int tid  = threadIdx.x;
    const int warp = tid >> 5;

    const int qk    = (tid & 7) * 4;    // lane-octet -> one 128B mu/s line
    const int rbase = tid >> 3;

    // B staging mapping: row = tid>>2 (0..31), 8 k per thread (one uint4)
    const int brow = tid >> 2;
    const int bkq  = (tid & 3) * 8;

    const int ec = tid & 63;
    const int eb = (tid >> 6) * 16;

    float bias;
    {
        int c = c0 + ec;
        float eps = tf_normal(bk0, bk1, (unsigned)(n * NOUT + c));
        bias = fmaf(eps, expf(vb[c]), mub[c]);
    }

    wmma::fragment<wmma::accumulator, 16, 16, 16, float> acc[2];
    wmma::fill_fragment(acc[0], 0.0f);
    wmma::fill_fragment(acc[1], 0.0f);

    const unsigned ebase = (unsigned)(n * NOUT + c0) * (unsigned)K;
    const __nv_bfloat16* bh = Bhi + (size_t)n * bStride;
    const __nv_bfloat16* bl = Blo + (size_t)n * bStride;

    for (int k0 = 0; k0 < K; k0 += KCH) {
        const int buf = (k0 >> 5) & 1;

        // ---- stage B chunk (coalesced; 1 uint4 per split per thread) ----
        {
            const size_t gsrc = (size_t)brow * K + k0 + bkq;
            uint4 vh = *reinterpret_cast<const uint4*>(bh + gsrc);
            uint4 vl = *reinterpret_cast<const uint4*>(bl + gsrc);
            const int soff = brow * BST + bkq;
            *reinterpret_cast<uint4*>(&sm.w.Bhi[buf][soff]) = vh;
            *reinterpret_cast<uint4*>(&sm.w.Blo[buf][soff]) = vl;
        }

        // ---- generate + split W chunk: 64c x 32k (thread: 16 k in 4 quads) ----
#pragma unroll 2
        for (int q = 0; q < 4; q++) {
            const int row = rbase + q * 16;
            const size_t goff = (size_t)(c0 + row) * K + k0 + qk;
            float4 m  = *reinterpret_cast<const float4*>(mu + goff);
            float4 sv = *reinterpret_cast<const float4*>(s  + goff);
            float r4[4];
            tf_normal4(wk0, wk1, ebase + (unsigned)(row * K + k0 + qk), one, r4);
            float w0 = fmaf(r4[0], sv.x, m.x);
            float w1 = fmaf(r4[1], sv.y, m.y);
            float w2 = fmaf(r4[2], sv.z, m.z);
            float w3 = fmaf(r4[3], sv.w, m.w);
            unsigned hp0 = pack_bf16x2(w1, w0);
            unsigned hp1 = pack_bf16x2(w3, w2);
            float h0 = __uint_as_float(hp0 << 16);
            float h1 = __uint_as_float(hp0 & 0xFFFF0000u);
            float h2 = __uint_as_float(hp1 << 16);
            float h3 = __uint_as_float(hp1 & 0xFFFF0000u);
            unsigned lp0 = pack_bf16x2(w1 - h1, w0 - h0);
            unsigned lp1 = pack_bf16x2(w3 - h3, w2 - h2);
            int off = row * WST + qk;
            *reinterpret_cast<uint2*>(&sm.w.Whi[buf][off]) = make_uint2(hp0, hp1);
            *reinterpret_cast<uint2*>(&sm.w.Wlo[buf][off]) = make_uint2(lp0, lp1);
        }
        __syncthreads();   // gen+staging(buf) visible; prior chunk's MMA reads done

        // ---- tensor-pipe GEMM on chunk: all operands now via LDSM ----
#pragma unroll
        for (int kk = 0; kk < KCH; kk += 16) {
            wmma::fragment<wmma::matrix_a, 16, 16, 16, __nv_bfloat16, wmma::row_major> ahi, alo;
            wmma::load_matrix_sync(ahi, &sm.w.Whi[buf][warp * 16 * WST + kk], WST);
            wmma::load_matrix_sync(alo, &sm.w.Wlo[buf][warp * 16 * WST + kk], WST);
#pragma unroll
            for (int nb = 0; nb < 2; nb++) {
                wmma::fragment<wmma::matrix_b, 16, 16, 16, __nv_bfloat16, wmma::col_major> bhf, blf;
                wmma::load_matrix_sync(bhf, &sm.w.Bhi[buf][nb * 16 * BST + kk], BST);
                wmma::load_matrix_sync(blf, &sm.w.Blo[buf][nb * 16 * BST + kk], BST);
                wmma::mma_sync(acc[nb], ahi, bhf, acc[nb]);
                wmma::mma_sync(acc[nb], ahi, blf, acc[nb]);
                wmma::mma_sync(acc[nb], alo, bhf, acc[nb]);
            }
        }
    }

    __syncthreads();
    wmma::store_matrix_sync(&sm.Dsm[warp * 16 * DST + 0],  acc[0], DST, wmma::mem_row_major);
    wmma::store_matrix_sync(&sm.Dsm[warp * 16 * DST + 16], acc[1], DST, wmma::mem_row_major);
    __syncthreads();

#pragma unroll
    for (int b = eb; b < eb + 16; b++) {
        float v = sm.Dsm[ec * DST + b] + bias;
        if (!LAST) {
            v = fmaxf(v, 0.0f);
            __nv_bfloat16 hi = __float2bfloat16_rn(v);
            __nv_bfloat16 lo = __float2bfloat16_rn(v - __bfloat162float(hi));
            size_t o = ((size_t)n * BATCH + b) * NOUT + (c0 + ec);
            g_Hhi[o] = hi; g_Hlo[o] = lo;
        } else {
            Out[((size_t)n * BATCH + b) * NOUT + (c0 + ec)] = v;
        }
    }
}

// -------------------- merged launch: L1 tiles then L2 tiles, static map ----------
__global__ __launch_bounds__(128, 5) void fused_all(
    const float* __restrict__ muW1, const float* __restrict__ mub1,
    const float* __restrict__ vb1,
    const float* __restrict__ muW2, const float* __restrict__ mub2,
    const float* __restrict__ vb2,
    float* __restrict__ out,
    unsigned k10, unsigned k11, unsigned k20, unsigned k21,
    unsigned k30, unsigned k31, unsigned k40, unsigned k41,
    unsigned one)
{
    __shared__ SmemU sm;
    const int bid = blockIdx.x;

    if (bid < L1B) {
        const int n = bid >> 3;             // 8 tiles per sample
        const int c0 = (bid & 7) * 64;
        tile64<DIN, DH, false>(n, c0, sm, muW1, g_sW1, mub1, vb1,
                               g_xhi, g_xlo, nullptr,
                               k10, k11, k20, k21, one, 0LL);
        __syncthreads();
        if (threadIdx.x == 0) {
            __threadfence();                // release H
            atomicAdd(&g_done1[n], 1);
        }
    } else {
        const int b2 = bid - L1B;
        const int n = b2 >> 2;              // 4 tiles per sample
        const int c0 = (b2 & 3) * 64;
        if (threadIdx.x == 0) {
            while (*(volatile int*)&g_done1[n] < 8) __nanosleep(64);
            __threadfence();                // acquire H
        }
        __syncthreads();
        tile64<DH, DOUT, true>(n, c0, sm, muW2, g_sW2, mub2, vb2,
                               g_Hhi, g_Hlo, out,
                               k30, k31, k40, k41, one, (long long)(BATCH * DH));
    }
}

// -------------------- host-side threefry for subkey derivation --------------------
static inline unsigned h_rotl(unsigned x, int r) { return (x << r) | (x >> (32 - r)); }
static void h_tf2x32(unsigned k0, unsigned k1, unsigned x0, unsigned x1,
                     unsigned& o0, unsigned& o1)
{
    const unsigned ks2 = k0 ^ k1 ^ 0x1BD11BDAu;
    x0 += k0; x1 += k1;
    static const int R[2][4] = {{13, 15, 26, 6}, {17, 29, 16, 24}};
    const unsigned ks[3] = {k0, k1, ks2};
    for (int g = 0; g < 5; g++) {
        for (int r = 0; r < 4; r++) {
            x0 += x1; x1 = h_rotl(x1, R[g & 1][r]); x1 ^= x0;
        }
        x0 += ks[(g + 1) % 3];
        x1 += ks[(g + 2) % 3] + (unsigned)(g + 1);
    }
    o0 = x0; o1 = x1;
}

extern "C" void kernel_launch(void* const* d_in, const int* in_sizes, int n_in,
                              void* d_out, int out_size)
{
    const float* x    = (const float*)d_in[0];
    const float* muW1 = (const float*)d_in[1];
    const float* mub1 = (const float*)d_in[2];
    const float* muW2 = (const float*)d_in[3];
    const float* mub2 = (const float*)d_in[4];
    const float* vW1  = (const float*)d_in[5];
    const float* vb1  = (const float*)d_in[6];
    const float* vW2  = (const float*)d_in[7];
    const float* vb2  = (const float*)d_in[8];
    float* out = (float*)d_out;

    unsigned keys[4][2];
    for (unsigned i = 0; i < 4; i++)
        h_tf2x32(0u, 42u, 0u, i, keys[i][0], keys[i][1]);

    prep_kernel<<<(DH * DIN + 255) / 256, 256>>>(x, vW1, vW2);

    fused_all<<<L1B + L2B, 128>>>(
        muW1, mub1, vb1, muW2, mub2, vb2, out,
        keys[0][0], keys[0][1], keys[1][0], keys[1][1],
        keys[2][0], keys[2][1], keys[3][0], keys[3][1],
        1u);
}